// round 6
// baseline (speedup 1.0000x reference)
#include <cuda_runtime.h>
#include <cuda_bf16.h>
#include <cuda_fp16.h>
#include <math.h>
#include <stdint.h>

// ---------------- problem constants ----------------------------------------
#define MOLS   1024
#define APM    24
#define NATOMS (MOLS * APM)       // 24576
#define H      128
#define F      128
#define G      50
#define T      3
#define NPAIR  (APM * (APM - 1) / 2)   // 276 = 12 * 23

#define NTAB   4096
#define RMAX   8.6610f
#define STEPF  (RMAX / (float)NTAB)
#define INV_STEP ((float)NTAB / RMAX)

#define OFFSTEP (10.0f / 49.0f)
#define GCOEFF  (-0.5f / (OFFSTEP * OFFSTEP))
#define PI_OVER_CUT 0.31415926535897932f
#define LOG2F_ 0.69314718055994531f

// ---------------- scratch (device globals) ---------------------------------
__device__ float         g_h[NATOMS * H];
__device__ float         g_xf[NATOMS * F];
__device__ float         g_agg[NATOMS * F];
__device__ float         g_tmp[NATOMS * H];
__device__ __half2       g_tab2[T * NTAB * F];
__device__ __nv_bfloat16 g_wb[9 * 128 * 128];   // bf16 weights, [w][n][k]

// ---------------- helpers --------------------------------------------------
__device__ __forceinline__ float sspf(float x) {
    if (x > 15.0f) return x - LOG2F_;
    return log1pf(expf(x)) - LOG2F_;
}

__device__ __forceinline__ uint32_t smem_u32(const void* p) {
    uint32_t a;
    asm("{ .reg .u64 t; cvta.to.shared.u64 t, %1; cvt.u32.u64 %0, t; }" : "=r"(a) : "l"(p));
    return a;
}

__device__ __forceinline__ void ldm_x4(uint32_t* r, uint32_t addr) {
    asm volatile("ldmatrix.sync.aligned.m8n8.x4.shared.b16 {%0,%1,%2,%3}, [%4];"
                 : "=r"(r[0]), "=r"(r[1]), "=r"(r[2]), "=r"(r[3]) : "r"(addr));
}

__device__ __forceinline__ void mma16816(float* c, uint32_t a0, uint32_t a1,
                                         uint32_t a2, uint32_t a3,
                                         uint32_t b0, uint32_t b1) {
    asm volatile(
        "mma.sync.aligned.m16n8k16.row.col.f32.bf16.bf16.f32 "
        "{%0,%1,%2,%3}, {%4,%5,%6,%7}, {%8,%9}, {%0,%1,%2,%3};"
        : "+f"(c[0]), "+f"(c[1]), "+f"(c[2]), "+f"(c[3])
        : "r"(a0), "r"(a1), "r"(a2), "r"(a3), "r"(b0), "r"(b1));
}

__device__ __forceinline__ uint32_t packbf(float2 v) {
    __nv_bfloat162 h = __floats2bfloat162_rn(v.x, v.y);
    return *(uint32_t*)&h;
}

// ---------------- embedding ------------------------------------------------
__global__ void k_embed(const int* __restrict__ z, const float* __restrict__ emb) {
    int idx = blockIdx.x * blockDim.x + threadIdx.x;
    if (idx < NATOMS * H) {
        int n = idx >> 7;
        int f = idx & 127;
        g_h[idx] = emb[z[n] * H + f];
    }
}

// ---------------- weight prep: transpose + bf16 ----------------------------
// g_wb[w][n][k] = bf16(Wsrc[t][k][n]),  w = t*3 + j, j in {lin1, lin2, lin}
__global__ void k_wprep(const float* __restrict__ l1, const float* __restrict__ l2,
                        const float* __restrict__ lw) {
    int idx = blockIdx.x * 256 + threadIdx.x;   // 9*16384 total
    int w = idx >> 14, r = idx & 16383;
    int n = r >> 7, k = r & 127;
    int t = w / 3, j = w - 3 * t;
    const float* s = (j == 0) ? l1 : ((j == 1) ? l2 : lw);
    g_wb[idx] = __float2bfloat16(s[t * 16384 + k * 128 + n]);
}

// ---------------- filter table build (fp16 interleaved) --------------------
#define TAB_ROWS_PER_BLK 8
#define TAB_CALC_ROWS    9
#define TAB_BLKS_PER_T   (NTAB / TAB_ROWS_PER_BLK)

__global__ void k_table(const float* __restrict__ w1, const float* __restrict__ b1,
                        const float* __restrict__ w2, const float* __restrict__ b2) {
    int t  = blockIdx.x / TAB_BLKS_PER_T;
    int rb = (blockIdx.x % TAB_BLKS_PER_T) * TAB_ROWS_PER_BLK;
    int f  = threadIdx.x;

    __shared__ float ea[TAB_CALC_ROWS][G];
    __shared__ float hid[TAB_CALC_ROWS][F];

    for (int idx = f; idx < TAB_CALC_ROWS * G; idx += 128) {
        int p = idx / G, g = idx % G;
        float r = (float)(rb + p) * STEPF;
        float d = r - (float)g * OFFSTEP;
        ea[p][g] = expf(GCOEFF * d * d);
    }
    __syncthreads();

    float acc[TAB_CALC_ROWS];
    float bb = b1[t * F + f];
#pragma unroll
    for (int p = 0; p < TAB_CALC_ROWS; p++) acc[p] = bb;
    for (int g = 0; g < G; g++) {
        float w = w1[(t * G + g) * F + f];
#pragma unroll
        for (int p = 0; p < TAB_CALC_ROWS; p++) acc[p] += ea[p][g] * w;
    }
#pragma unroll
    for (int p = 0; p < TAB_CALC_ROWS; p++) hid[p][f] = sspf(acc[p]);
    __syncthreads();

    float b2v = b2[t * F + f];
#pragma unroll
    for (int p = 0; p < TAB_CALC_ROWS; p++) acc[p] = b2v;
    for (int k = 0; k < F; k++) {
        float w = w2[(t * F + k) * F + f];
#pragma unroll
        for (int p = 0; p < TAB_CALC_ROWS; p++) acc[p] += hid[p][k] * w;
    }
#pragma unroll
    for (int p = 0; p < TAB_CALC_ROWS; p++) {
        float r = (float)(rb + p) * STEPF;
        float C = 0.5f * (cosf(r * PI_OVER_CUT) + 1.0f);
        acc[p] *= C;
    }
#pragma unroll
    for (int p = 0; p < TAB_ROWS_PER_BLK; p++)
        g_tab2[((size_t)t * NTAB + rb + p) * F + f] = __floats2half2_rn(acc[p], acc[p + 1]);
}

// ---------------- bf16 HMMA GEMM: C[24576x128] = act(A @ Bw^T + bias) ------
// A fp32 [m][k] from gmem (converted on the fly), Bw bf16 [n][k].
// MODE 0: C = D ; MODE 1: C = ssp(D + bias) ; MODE 2: C += D + bias
#define BPITCH 136   // bf16 elems per smem row (+16B pad: conflict-free ldmatrix)

template<int MODE>
__global__ void __launch_bounds__(128) gemm_mma(const float* __restrict__ Ag,
                                                const __nv_bfloat16* __restrict__ Bw,
                                                const float* __restrict__ bias,
                                                float* __restrict__ Cg) {
    __shared__ __align__(16) __nv_bfloat16 sB[128 * BPITCH];

    int tid = threadIdx.x, lane = tid & 31, warp = tid >> 5;
    int m0 = blockIdx.x * 64;

    // stage B [128n x 128k] bf16 -> padded smem
    const uint4* Bv = (const uint4*)Bw;
#pragma unroll
    for (int it = 0; it < 16; it++) {
        int e = it * 128 + tid;          // uint4 index (8 bf16)
        int n = e >> 4, kc = (e & 15) * 8;
        *(uint4*)(sB + n * BPITCH + kc) = Bv[e];
    }
    __syncthreads();

    int rbase = m0 + warp * 16 + (lane >> 2);
    const float* Ar0 = Ag + (size_t)rbase * 128;
    const float* Ar1 = Ag + (size_t)(rbase + 8) * 128;
    int kc0 = (lane & 3) * 2;

    float acc[16][4];
#pragma unroll
    for (int n = 0; n < 16; n++) {
        acc[n][0] = acc[n][1] = acc[n][2] = acc[n][3] = 0.f;
    }

    // ldmatrix address for B: n = (lane>>4)*8 + (lane&7), k-off = ((lane>>3)&1)*8
    uint32_t bbase = smem_u32(sB) +
        ((((lane >> 4) << 3) | (lane & 7)) * BPITCH + (((lane >> 3) & 1) << 3)) * 2;

#pragma unroll
    for (int k = 0; k < 8; k++) {
        uint32_t a0 = packbf(*(const float2*)(Ar0 + k * 16 + kc0));
        uint32_t a1 = packbf(*(const float2*)(Ar1 + k * 16 + kc0));
        uint32_t a2 = packbf(*(const float2*)(Ar0 + k * 16 + 8 + kc0));
        uint32_t a3 = packbf(*(const float2*)(Ar1 + k * 16 + 8 + kc0));
#pragma unroll
        for (int g = 0; g < 8; g++) {     // n16 groups
            uint32_t b[4];
            ldm_x4(b, bbase + (uint32_t)(g * 16 * BPITCH + k * 16) * 2);
            mma16816(acc[2 * g],     a0, a1, a2, a3, b[0], b[1]);
            mma16816(acc[2 * g + 1], a0, a1, a2, a3, b[2], b[3]);
        }
    }

#pragma unroll
    for (int nt = 0; nt < 16; nt++) {
        int col = nt * 8 + kc0;
        float2 v0 = make_float2(acc[nt][0], acc[nt][1]);
        float2 v1 = make_float2(acc[nt][2], acc[nt][3]);
        if (MODE > 0) {
            float2 b = *(const float2*)(bias + col);
            v0.x += b.x; v0.y += b.y; v1.x += b.x; v1.y += b.y;
        }
        if (MODE == 1) {
            v0.x = sspf(v0.x); v0.y = sspf(v0.y);
            v1.x = sspf(v1.x); v1.y = sspf(v1.y);
        }
        float2* d0 = (float2*)(Cg + (size_t)rbase * 128 + col);
        float2* d1 = (float2*)(Cg + (size_t)(rbase + 8) * 128 + col);
        if (MODE == 2) {
            float2 o0 = *d0, o1 = *d1;
            v0.x += o0.x; v0.y += o0.y; v1.x += o1.x; v1.y += o1.y;
        }
        *d0 = v0;
        *d1 = v1;
    }
}

// ---------------- per-molecule edge message + aggregation ------------------
__device__ __forceinline__ void pij(int p, int& i, int& j) {
    int pp = p, ii = 0;
    while (pp >= APM - 1 - ii) { pp -= APM - 1 - ii; ii++; }
    i = ii; j = ii + 1 + pp;
}

__global__ void __launch_bounds__(128, 4) k_edge(const float* __restrict__ pos, int t) {
    int m = blockIdx.x;
    int f = threadIdx.x;
    __shared__ float ps[APM][3];
    __shared__ int   ibase[NPAIR];
    __shared__ float frs[NPAIR];

    int base = m * APM;
    for (int idx = f; idx < APM * 3; idx += 128)
        ps[idx / 3][idx % 3] = pos[(size_t)base * 3 + idx];

    float xfr[APM], acc[APM];
#pragma unroll
    for (int a = 0; a < APM; a++) {
        xfr[a] = g_xf[(size_t)(base + a) * F + f];
        acc[a] = 0.0f;
    }
    __syncthreads();

    for (int p = f; p < NPAIR; p += 128) {
        int i, j; pij(p, i, j);
        float dx = ps[i][0] - ps[j][0];
        float dy = ps[i][1] - ps[j][1];
        float dz = ps[i][2] - ps[j][2];
        float dist = sqrtf(dx * dx + dy * dy + dz * dz);
        float u = dist * INV_STEP;
        int i0 = (int)u;
        ibase[p] = i0;
        frs[p]   = u - (float)i0;
    }
    __syncthreads();

    const __half2* tab = g_tab2 + (size_t)t * NTAB * F + f;
    uint32_t wv[12];
#pragma unroll
    for (int q = 0; q < 12; q++)
        wv[q] = *(const uint32_t*)(tab + (size_t)ibase[q] * F);
#pragma unroll
    for (int b = 0; b < 23; b++) {
        uint32_t cur[12];
#pragma unroll
        for (int q = 0; q < 12; q++) cur[q] = wv[q];
        if (b < 22) {
#pragma unroll
            for (int q = 0; q < 12; q++)
                wv[q] = *(const uint32_t*)(tab + (size_t)ibase[(b + 1) * 12 + q] * F);
        }
#pragma unroll
        for (int q = 0; q < 12; q++) {
            int p = b * 12 + q, i, j;
            pij(p, i, j);
            __half2 hv = *(__half2*)&cur[q];
            float2 rv = __half22float2(hv);
            float w = fmaf(frs[p], rv.y - rv.x, rv.x);
            acc[i] = fmaf(xfr[j], w, acc[i]);
            acc[j] = fmaf(xfr[i], w, acc[j]);
        }
    }
#pragma unroll
    for (int a = 0; a < APM; a++)
        g_agg[(size_t)(base + a) * F + f] = acc[a];
}

// ---------------- output head ----------------------------------------------
__global__ void k_head(const float* __restrict__ w1, const float* __restrict__ b1,
                       const float* __restrict__ w2, const float* __restrict__ b2,
                       float* __restrict__ out) {
    int m   = blockIdx.x;
    int tid = threadIdx.x;
    int a2  = tid >> 6;
    int j   = tid & 63;
    __shared__ float hs[APM][H];
    __shared__ float ws[4];
    __shared__ float molsum;

    for (int idx = tid; idx < APM * H; idx += 128)
        hs[idx / H][idx % H] = g_h[(size_t)m * APM * H + idx];
    if (tid == 0) molsum = 0.0f;
    __syncthreads();

    float w2j = w2[j];
    float b1j = b1[j];
    float b2v = b2[0];
    for (int pr = 0; pr < APM / 2; pr++) {
        int a = pr * 2 + a2;
        float acc = b1j;
#pragma unroll 8
        for (int k = 0; k < H; k++) acc += hs[a][k] * w1[k * 64 + j];
        float val = sspf(acc) * w2j;
#pragma unroll
        for (int off = 16; off > 0; off >>= 1)
            val += __shfl_down_sync(0xffffffffu, val, off);
        if ((tid & 31) == 0) ws[tid >> 5] = val;
        __syncthreads();
        if (tid == 0) molsum += ws[0] + ws[1] + ws[2] + ws[3] + 2.0f * b2v;
        __syncthreads();
    }
    if (tid == 0) out[m] = molsum;
}

// ---------------- launch ---------------------------------------------------
extern "C" void kernel_launch(void* const* d_in, const int* in_sizes, int n_in,
                              void* d_out, int out_size) {
    const int*   z       = (const int*)d_in[0];
    const float* pos     = (const float*)d_in[1];
    const float* emb     = (const float*)d_in[4];
    const float* mlp_w1  = (const float*)d_in[5];
    const float* mlp_b1  = (const float*)d_in[6];
    const float* mlp_w2  = (const float*)d_in[7];
    const float* mlp_b2  = (const float*)d_in[8];
    const float* lin1_w  = (const float*)d_in[9];
    const float* lin2_w  = (const float*)d_in[10];
    const float* lin2_b  = (const float*)d_in[11];
    const float* lin_w   = (const float*)d_in[12];
    const float* lin_b   = (const float*)d_in[13];
    const float* out_w1  = (const float*)d_in[14];
    const float* out_b1  = (const float*)d_in[15];
    const float* out_w2  = (const float*)d_in[16];
    const float* out_b2  = (const float*)d_in[17];
    float* out = (float*)d_out;

    (void)in_sizes; (void)n_in; (void)out_size;

    float *p_h = 0, *p_xf = 0, *p_agg = 0, *p_tmp = 0;
    __nv_bfloat16* p_wb = 0;
    cudaGetSymbolAddress((void**)&p_h,   g_h);
    cudaGetSymbolAddress((void**)&p_xf,  g_xf);
    cudaGetSymbolAddress((void**)&p_agg, g_agg);
    cudaGetSymbolAddress((void**)&p_tmp, g_tmp);
    cudaGetSymbolAddress((void**)&p_wb,  g_wb);

    k_embed<<<(NATOMS * H + 255) / 256, 256>>>(z, emb);
    k_wprep<<<9 * 16384 / 256, 256>>>(lin1_w, lin2_w, lin_w);
    k_table<<<T * TAB_BLKS_PER_T, 128>>>(mlp_w1, mlp_b1, mlp_w2, mlp_b2);

    for (int t = 0; t < T; t++) {
        gemm_mma<0><<<NATOMS / 64, 128>>>(p_h, p_wb + (size_t)(t * 3 + 0) * 16384,
                                          nullptr, p_xf);
        k_edge<<<MOLS, 128>>>(pos, t);
        gemm_mma<1><<<NATOMS / 64, 128>>>(p_agg, p_wb + (size_t)(t * 3 + 1) * 16384,
                                          lin2_b + (size_t)t * F, p_tmp);
        gemm_mma<2><<<NATOMS / 64, 128>>>(p_tmp, p_wb + (size_t)(t * 3 + 2) * 16384,
                                          lin_b + (size_t)t * H, p_h);
    }

    k_head<<<MOLS, 128>>>(out_w1, out_b1, out_w2, out_b2, out);
}